// round 11
// baseline (speedup 1.0000x reference)
#include <cuda_runtime.h>
#include <cstdint>

// PointConv: B=32, C=64, H=W=64, KH=KW=2 -> L=1024, n=256.
// Per l: D[p, b] = sum_k W[l][k][p] * patch[b][k] + bias[p, l]
// fp32 via 3-term bf16 split on mma.sync.m16n8k16.
// R11: weights LDG->registers (1-stage lookahead), no TMA, no W smem.

#define HH 64
#define CC 64
#define NN 256
#define LL 1024

#define KSTAGE 16
#define NSTG   16

#define AROW  512                              // 256 p x bf16, XOR-swizzled
#define ATILE (KSTAGE * AROW)                  // 8192 (one of hi/mid)
#define ABUF  (2 * ATILE)                      // 16384 (hi + mid)

#define OFF_A    0                             // 2 x 16384 = 32768
#define OFF_PH   32768                         // 32 x 512 = 16384
#define OFF_PM   49152                         // 16384
#define SMEM_TOTAL 65536

__device__ __forceinline__ uint32_t swz(uint32_t row, uint32_t cb) {
    return row * AROW + (cb ^ ((row & 7) << 4));
}
__device__ __forceinline__ uint32_t cvt2(float lo, float hi) {  // pack {lo=low16, hi=high16}
    uint32_t r;
    asm("cvt.rn.bf16x2.f32 %0, %1, %2;" : "=r"(r) : "f"(hi), "f"(lo));
    return r;
}
__device__ __forceinline__ float lo_f(uint32_t p) { return __uint_as_float(p << 16); }
__device__ __forceinline__ float hi_f(uint32_t p) { return __uint_as_float(p & 0xffff0000u); }

__device__ __forceinline__ void ldsm4t(uint32_t& r0, uint32_t& r1, uint32_t& r2, uint32_t& r3,
                                       uint32_t addr) {
    asm volatile("ldmatrix.sync.aligned.m8n8.x4.trans.shared.b16 {%0,%1,%2,%3}, [%4];"
                 : "=r"(r0), "=r"(r1), "=r"(r2), "=r"(r3) : "r"(addr));
}
__device__ __forceinline__ void mma_bf16(float* d, const uint32_t* a, const uint32_t* b) {
    asm volatile(
        "mma.sync.aligned.m16n8k16.row.col.f32.bf16.bf16.f32 "
        "{%0,%1,%2,%3}, {%4,%5,%6,%7}, {%8,%9}, {%0,%1,%2,%3};"
        : "+f"(d[0]), "+f"(d[1]), "+f"(d[2]), "+f"(d[3])
        : "r"(a[0]), "r"(a[1]), "r"(a[2]), "r"(a[3]), "r"(b[0]), "r"(b[1]));
}

__global__ void __launch_bounds__(256, 2)
pointconv_mma(const float* __restrict__ x,
              const float* __restrict__ w,
              const float* __restrict__ bias,
              float* __restrict__ out)
{
    extern __shared__ char smem[];
    const uint32_t sbase = (uint32_t)__cvta_generic_to_shared(smem);
    const int tid  = threadIdx.x;
    const int wid  = tid >> 5;
    const int lane = tid & 31;
    const int l  = blockIdx.x;
    const int ph = l >> 5, pw = l & 31;
    const float* __restrict__ wl = w + (size_t)l * (NN * NN);

    // ---- patch gather + bf16 hi/mid split -> [b][k] swizzled ----
    {
        const int b  = tid & 31;
        const int cg = tid >> 5;
        #pragma unroll
        for (int ci = 0; ci < 8; ci++) {
            const int c = cg * 8 + ci;
            #pragma unroll
            for (int kh = 0; kh < 2; kh++) {
                const float2 v = *reinterpret_cast<const float2*>(
                    x + (size_t)(((b * CC + c) * HH + 2 * ph + kh) * HH + 2 * pw));
                const int k = c * 4 + kh * 2;
                const uint32_t hp = cvt2(v.x, v.y);
                const uint32_t mp = cvt2(v.x - lo_f(hp), v.y - hi_f(hp));
                const uint32_t a = swz((uint32_t)b, (uint32_t)(k * 2));
                *reinterpret_cast<uint32_t*>(smem + OFF_PH + a) = hp;
                *reinterpret_cast<uint32_t*>(smem + OFF_PM + a) = mp;
            }
        }
    }

    float d[2][4][4];
    #pragma unroll
    for (int i = 0; i < 2; i++)
        #pragma unroll
        for (int j = 0; j < 4; j++)
            #pragma unroll
            for (int r = 0; r < 4; r++) d[i][j][r] = 0.0f;

    const int wbase = wid * 32;
    const int bq = lane >> 2;
    const int kq = (lane & 3) * 2;
    const int lm_m = lane >> 3, lm_r = lane & 7;

    // ---- weight LDG prologue: stage 0 into reg set 0 ----
    float4 rA[2][2], rB[2][2];
    #pragma unroll
    for (int j = 0; j < 2; j++) {
        const float* src = wl + (size_t)(wid + j * 8) * NN + lane * 4;
        rA[0][j] = *reinterpret_cast<const float4*>(src);
        rB[0][j] = *reinterpret_cast<const float4*>(src + 128);
    }

    // ---- mainloop over 16 k-stages: LDG lookahead -> convert/STS -> sync -> mma ----
    #pragma unroll 1
    for (int s = 0; s < NSTG; s++) {
        const int cur = s & 1, nxt = cur ^ 1;

        // issue next stage's loads first (in flight during convert + mma)
        if (s + 1 < NSTG) {
            #pragma unroll
            for (int j = 0; j < 2; j++) {
                const float* src = wl + (size_t)((s + 1) * KSTAGE + wid + j * 8) * NN + lane * 4;
                rA[nxt][j] = *reinterpret_cast<const float4*>(src);
                rB[nxt][j] = *reinterpret_cast<const float4*>(src + 128);
            }
        }

        // convert current stage from registers -> A tiles (hi at A, mid at A+ATILE)
        char* A = smem + OFF_A + cur * ABUF;
        #pragma unroll
        for (int j = 0; j < 2; j++) {
            const int r = wid + j * 8;
            const float4 va = rA[cur][j];
            const float4 vb = rB[cur][j];
            const uint32_t ha0 = cvt2(va.x, va.y), ha1 = cvt2(va.z, va.w);
            const uint32_t hb0 = cvt2(vb.x, vb.y), hb1 = cvt2(vb.z, vb.w);
            const uint32_t ma0 = cvt2(va.x - lo_f(ha0), va.y - hi_f(ha0));
            const uint32_t ma1 = cvt2(va.z - lo_f(ha1), va.w - hi_f(ha1));
            const uint32_t mb0 = cvt2(vb.x - lo_f(hb0), vb.y - hi_f(hb0));
            const uint32_t mb1 = cvt2(vb.z - lo_f(hb1), vb.w - hi_f(hb1));
            const uint32_t a0 = swz((uint32_t)r, (uint32_t)(lane * 8));
            const uint32_t a1 = swz((uint32_t)r, (uint32_t)(256 + lane * 8));
            *reinterpret_cast<uint2*>(A + a0)         = make_uint2(ha0, ha1);
            *reinterpret_cast<uint2*>(A + a1)         = make_uint2(hb0, hb1);
            *reinterpret_cast<uint2*>(A + ATILE + a0) = make_uint2(ma0, ma1);
            *reinterpret_cast<uint2*>(A + ATILE + a1) = make_uint2(mb0, mb1);
        }
        __syncthreads();

        // B fragments for this stage's k16 chunk
        const int kg = s * KSTAGE;
        uint32_t bh[4][2], bm[4][2];
        #pragma unroll
        for (int nt = 0; nt < 4; nt++) {
            const uint32_t row = (uint32_t)(nt * 8 + bq);
            const uint32_t o0 = swz(row, (uint32_t)((kg + kq) * 2));
            const uint32_t o1 = swz(row, (uint32_t)((kg + kq) * 2 + 16));
            bh[nt][0] = *reinterpret_cast<uint32_t*>(smem + OFF_PH + o0);
            bh[nt][1] = *reinterpret_cast<uint32_t*>(smem + OFF_PH + o1);
            bm[nt][0] = *reinterpret_cast<uint32_t*>(smem + OFF_PM + o0);
            bm[nt][1] = *reinterpret_cast<uint32_t*>(smem + OFF_PM + o1);
        }

        const uint32_t Asm = sbase + OFF_A + cur * ABUF;
        #pragma unroll
        for (int pt = 0; pt < 2; pt++) {
            const uint32_t row = (uint32_t)(lm_r + (lm_m >> 1) * 8);
            const uint32_t cb  = (uint32_t)((wbase + pt * 16 + (lm_m & 1) * 8) * 2);
            const uint32_t lmoff = swz(row, cb);
            uint32_t ah[4], am[4];
            ldsm4t(ah[0], ah[1], ah[2], ah[3], Asm + lmoff);
            ldsm4t(am[0], am[1], am[2], am[3], Asm + ATILE + lmoff);
            #pragma unroll
            for (int nt = 0; nt < 4; nt++) {
                mma_bf16(d[pt][nt], ah, bh[nt]);
                mma_bf16(d[pt][nt], ah, bm[nt]);
                mma_bf16(d[pt][nt], am, bh[nt]);
            }
        }
    }

    // ---- epilogue: bias + scatter ----
    #pragma unroll
    for (int pt = 0; pt < 2; pt++) {
        const int p0 = wbase + pt * 16 + (lane >> 2);
        const int p1 = p0 + 8;
        const float bv0 = bias[p0 * LL + l];
        const float bv1 = bias[p1 * LL + l];
        const int c0 = p0 >> 2, kh0 = (p0 >> 1) & 1, kw0 = p0 & 1;
        const int c1 = p1 >> 2, kh1 = (p1 >> 1) & 1, kw1 = p1 & 1;
        #pragma unroll
        for (int nt = 0; nt < 4; nt++) {
            const int b = nt * 8 + 2 * (lane & 3);
            const size_t o0 = (size_t)(((b * CC + c0) * HH + 2 * ph + kh0) * HH + 2 * pw + kw0);
            const size_t o1 = (size_t)(((b * CC + c1) * HH + 2 * ph + kh1) * HH + 2 * pw + kw1);
            const size_t bs = (size_t)CC * HH * HH;
            out[o0]      = d[pt][nt][0] + bv0;
            out[o0 + bs] = d[pt][nt][1] + bv0;
            out[o1]      = d[pt][nt][2] + bv1;
            out[o1 + bs] = d[pt][nt][3] + bv1;
        }
    }
}

extern "C" void kernel_launch(void* const* d_in, const int* in_sizes, int n_in,
                              void* d_out, int out_size)
{
    const float* x    = (const float*)d_in[0];
    const float* w    = (const float*)d_in[1];
    const float* bias = (const float*)d_in[2];
    float* out        = (float*)d_out;

    cudaFuncSetAttribute(pointconv_mma,
                         cudaFuncAttributeMaxDynamicSharedMemorySize, SMEM_TOTAL);
    pointconv_mma<<<LL, 256, SMEM_TOTAL>>>(x, w, bias, out);
}

// round 12
// speedup vs baseline: 1.1420x; 1.1420x over previous
#include <cuda_runtime.h>
#include <cstdint>

// PointConv: B=32, C=64, H=W=64, KH=KW=2 -> L=1024, n=256.
// Per l: D[p, b] = sum_k W[l][k][p] * patch[b][k] + bias[p, l]
// fp32 via 3-term bf16 split on mma.sync.m16n8k16.
// R12: warp-independent pipelines. Each warp owns p-slice [32w,32w+32):
//      private W LDG stream (2-stage lookahead), private A tile, no
//      __syncthreads in mainloop (only __syncwarp).

#define HH 64
#define CC 64
#define NN 256
#define LL 1024

#define KSTAGE 16
#define NSTG   16

#define AWARP 4096                 // per-warp A buf: hi 2KB + mid 2KB
#define OFF_A    0                 // 8 x 4096 = 32768
#define OFF_PH   32768             // patch hi: 32 x 512 = 16384
#define OFF_PM   49152             // patch mid
#define SMEM_TOTAL 65536

#define PROW 512                   // patch row stride (b rows, XOR swizzle)

__device__ __forceinline__ uint32_t pswz(uint32_t row, uint32_t cb) {
    return row * PROW + (cb ^ ((row & 7) << 4));
}
__device__ __forceinline__ uint32_t aswz(uint32_t r, uint32_t cb) {   // per-warp A tile
    return r * 128 + (cb ^ ((r & 7) << 4));
}
__device__ __forceinline__ uint32_t cvt2(float lo, float hi) {  // pack {lo=low16, hi=high16}
    uint32_t r;
    asm("cvt.rn.bf16x2.f32 %0, %1, %2;" : "=r"(r) : "f"(hi), "f"(lo));
    return r;
}
__device__ __forceinline__ float lo_f(uint32_t p) { return __uint_as_float(p << 16); }
__device__ __forceinline__ float hi_f(uint32_t p) { return __uint_as_float(p & 0xffff0000u); }

__device__ __forceinline__ void ldsm4t(uint32_t& r0, uint32_t& r1, uint32_t& r2, uint32_t& r3,
                                       uint32_t addr) {
    asm volatile("ldmatrix.sync.aligned.m8n8.x4.trans.shared.b16 {%0,%1,%2,%3}, [%4];"
                 : "=r"(r0), "=r"(r1), "=r"(r2), "=r"(r3) : "r"(addr));
}
__device__ __forceinline__ void mma_bf16(float* d, const uint32_t* a, const uint32_t* b) {
    asm volatile(
        "mma.sync.aligned.m16n8k16.row.col.f32.bf16.bf16.f32 "
        "{%0,%1,%2,%3}, {%4,%5,%6,%7}, {%8,%9}, {%0,%1,%2,%3};"
        : "+f"(d[0]), "+f"(d[1]), "+f"(d[2]), "+f"(d[3])
        : "r"(a[0]), "r"(a[1]), "r"(a[2]), "r"(a[3]), "r"(b[0]), "r"(b[1]));
}

__global__ void __launch_bounds__(256, 2)
pointconv_mma(const float* __restrict__ x,
              const float* __restrict__ w,
              const float* __restrict__ bias,
              float* __restrict__ out)
{
    extern __shared__ char smem[];
    const uint32_t sbase = (uint32_t)__cvta_generic_to_shared(smem);
    const int tid  = threadIdx.x;
    const int wid  = tid >> 5;
    const int lane = tid & 31;
    const int l  = blockIdx.x;
    const int ph = l >> 5, pw = l & 31;
    const float* __restrict__ wl = w + (size_t)l * (NN * NN);

    // ---- patch gather + bf16 hi/mid split -> [b][k] swizzled ----
    {
        const int b  = tid & 31;
        const int cg = tid >> 5;
        #pragma unroll
        for (int ci = 0; ci < 8; ci++) {
            const int c = cg * 8 + ci;
            #pragma unroll
            for (int kh = 0; kh < 2; kh++) {
                const float2 v = *reinterpret_cast<const float2*>(
                    x + (size_t)(((b * CC + c) * HH + 2 * ph + kh) * HH + 2 * pw));
                const int k = c * 4 + kh * 2;
                const uint32_t hp = cvt2(v.x, v.y);
                const uint32_t mp = cvt2(v.x - lo_f(hp), v.y - hi_f(hp));
                const uint32_t a = pswz((uint32_t)b, (uint32_t)(k * 2));
                *reinterpret_cast<uint32_t*>(smem + OFF_PH + a) = hp;
                *reinterpret_cast<uint32_t*>(smem + OFF_PM + a) = mp;
            }
        }
    }

    float d[2][4][4];
    #pragma unroll
    for (int i = 0; i < 2; i++)
        #pragma unroll
        for (int j = 0; j < 4; j++)
            #pragma unroll
            for (int r = 0; r < 4; r++) d[i][j][r] = 0.0f;

    const int wbase = wid * 32;                 // warp's p slice
    const int bq = lane >> 2;
    const int kq = (lane & 3) * 2;
    const int lm_m = lane >> 3, lm_r = lane & 7;

    // per-lane W addressing: 4 LDG.128 per stage cover 16 rows x 32 p
    const int lrow = lane >> 3;                 // 0..3 (row within group of 4)
    const int lcol = (lane & 7) * 4;            // p offset within slice (fp32)
    const float* __restrict__ wslice = wl + wbase + lcol;

    // ---- 2-stage LDG lookahead prologue ----
    float4 rw[2][4];
    #pragma unroll
    for (int j = 0; j < 4; j++)
        rw[0][j] = *reinterpret_cast<const float4*>(wslice + (size_t)(j * 4 + lrow) * NN);
    #pragma unroll
    for (int j = 0; j < 4; j++)
        rw[1][j] = *reinterpret_cast<const float4*>(wslice + (size_t)(KSTAGE + j * 4 + lrow) * NN);

    __syncthreads();                            // patch visible to all warps

    char* Aw = smem + OFF_A + wid * AWARP;      // hi at Aw, mid at Aw+2048
    const uint32_t Asm = sbase + OFF_A + wid * AWARP;
    const uint32_t sts_col = (uint32_t)((lane & 7) * 8);

    // ---- mainloop: fully warp-local, no __syncthreads ----
    #pragma unroll 1
    for (int s = 0; s < NSTG; s++) {
        const int cur = s & 1;

        // consume current set into locals, then refill with stage s+2
        float4 v0 = rw[cur][0], v1 = rw[cur][1], v2 = rw[cur][2], v3 = rw[cur][3];
        if (s + 2 < NSTG) {
            #pragma unroll
            for (int j = 0; j < 4; j++)
                rw[cur][j] = *reinterpret_cast<const float4*>(
                    wslice + (size_t)((s + 2) * KSTAGE + j * 4 + lrow) * NN);
        }

        // convert + STS into private A tile
        {
            const float4 vv[4] = {v0, v1, v2, v3};
            #pragma unroll
            for (int j = 0; j < 4; j++) {
                const uint32_t r = (uint32_t)(j * 4 + lrow);   // local k row
                const float4 va = vv[j];
                const uint32_t h01 = cvt2(va.x, va.y), h23 = cvt2(va.z, va.w);
                const uint32_t m01 = cvt2(va.x - lo_f(h01), va.y - hi_f(h01));
                const uint32_t m23 = cvt2(va.z - lo_f(h23), va.w - hi_f(h23));
                const uint32_t a = aswz(r, sts_col);
                *reinterpret_cast<uint2*>(Aw + a)        = make_uint2(h01, h23);
                *reinterpret_cast<uint2*>(Aw + 2048 + a) = make_uint2(m01, m23);
            }
        }
        __syncwarp();

        // B fragments for this stage's k16 chunk (shared read-only patch)
        const int kg = s * KSTAGE;
        uint32_t bh[4][2], bm[4][2];
        #pragma unroll
        for (int nt = 0; nt < 4; nt++) {
            const uint32_t row = (uint32_t)(nt * 8 + bq);
            const uint32_t o0 = pswz(row, (uint32_t)((kg + kq) * 2));
            const uint32_t o1 = pswz(row, (uint32_t)((kg + kq) * 2 + 16));
            bh[nt][0] = *reinterpret_cast<uint32_t*>(smem + OFF_PH + o0);
            bh[nt][1] = *reinterpret_cast<uint32_t*>(smem + OFF_PH + o1);
            bm[nt][0] = *reinterpret_cast<uint32_t*>(smem + OFF_PM + o0);
            bm[nt][1] = *reinterpret_cast<uint32_t*>(smem + OFF_PM + o1);
        }

        #pragma unroll
        for (int pt = 0; pt < 2; pt++) {
            const uint32_t r  = (uint32_t)(lm_r + (lm_m >> 1) * 8);
            const uint32_t cb = (uint32_t)(pt * 32 + (lm_m & 1) * 16);
            const uint32_t lmoff = aswz(r, cb);
            uint32_t ah[4], am[4];
            ldsm4t(ah[0], ah[1], ah[2], ah[3], Asm + lmoff);
            ldsm4t(am[0], am[1], am[2], am[3], Asm + 2048 + lmoff);
            #pragma unroll
            for (int nt = 0; nt < 4; nt++) {
                mma_bf16(d[pt][nt], ah, bh[nt]);
                mma_bf16(d[pt][nt], ah, bm[nt]);
                mma_bf16(d[pt][nt], am, bh[nt]);
            }
        }
        __syncwarp();   // ldsm done before next stage's STS overwrites the tile
    }

    // ---- epilogue: bias + scatter ----
    #pragma unroll
    for (int pt = 0; pt < 2; pt++) {
        const int p0 = wbase + pt * 16 + (lane >> 2);
        const int p1 = p0 + 8;
        const float bv0 = bias[p0 * LL + l];
        const float bv1 = bias[p1 * LL + l];
        const int c0 = p0 >> 2, kh0 = (p0 >> 1) & 1, kw0 = p0 & 1;
        const int c1 = p1 >> 2, kh1 = (p1 >> 1) & 1, kw1 = p1 & 1;
        #pragma unroll
        for (int nt = 0; nt < 4; nt++) {
            const int b = nt * 8 + 2 * (lane & 3);
            const size_t o0 = (size_t)(((b * CC + c0) * HH + 2 * ph + kh0) * HH + 2 * pw + kw0);
            const size_t o1 = (size_t)(((b * CC + c1) * HH + 2 * ph + kh1) * HH + 2 * pw + kw1);
            const size_t bs = (size_t)CC * HH * HH;
            out[o0]      = d[pt][nt][0] + bv0;
            out[o0 + bs] = d[pt][nt][1] + bv0;
            out[o1]      = d[pt][nt][2] + bv1;
            out[o1 + bs] = d[pt][nt][3] + bv1;
        }
    }
}

extern "C" void kernel_launch(void* const* d_in, const int* in_sizes, int n_in,
                              void* d_out, int out_size)
{
    const float* x    = (const float*)d_in[0];
    const float* w    = (const float*)d_in[1];
    const float* bias = (const float*)d_in[2];
    float* out        = (float*)d_out;

    cudaFuncSetAttribute(pointconv_mma,
                         cudaFuncAttributeMaxDynamicSharedMemorySize, SMEM_TOTAL);
    pointconv_mma<<<LL, 256, SMEM_TOTAL>>>(x, w, bias, out);
}